// round 1
// baseline (speedup 1.0000x reference)
#include <cuda_runtime.h>
#include <math.h>

// Problem constants (B=8, S=2048, D=2048, H=2048, E=4, TOP_K=2)
#define NTOK 16384
#define DDIM 2048
#define HDIM 2048
#define NEXP 4

#define BM 128
#define BN 128
#define BK 8

// Scratch (static __device__ arrays — no runtime allocation)
__device__ int   g_cnt[NEXP];
__device__ int   g_tok[NEXP][NTOK];
__device__ float g_wgt[NEXP][NTOK];
__device__ float g_h1[(size_t)NEXP * NTOK * HDIM];   // 512 MB intermediate

// ---------------------------------------------------------------------------
// Zero output + reset per-expert counters (must run first each replay)
// ---------------------------------------------------------------------------
__global__ void zero_kernel(float4* __restrict__ out, long n4) {
    long i = (long)blockIdx.x * blockDim.x + threadIdx.x;
    long stride = (long)gridDim.x * blockDim.x;
    float4 z = make_float4(0.f, 0.f, 0.f, 0.f);
    for (; i < n4; i += stride) out[i] = z;
    if (blockIdx.x == 0 && threadIdx.x < NEXP) g_cnt[threadIdx.x] = 0;
}

// ---------------------------------------------------------------------------
// Router: logits -> top-2 -> renormalized weights -> per-expert token lists
// One warp per token. E=4 so everything fits in registers.
// ---------------------------------------------------------------------------
__global__ void router_kernel(const float* __restrict__ x,
                              const float* __restrict__ gw) {
    int warp = (blockIdx.x * blockDim.x + threadIdx.x) >> 5;
    int lane = threadIdx.x & 31;
    if (warp >= NTOK) return;

    const float* xr = x + (size_t)warp * DDIM;
    float a0 = 0.f, a1 = 0.f, a2 = 0.f, a3 = 0.f;
    for (int k = lane; k < DDIM; k += 32) {
        float xv = xr[k];
        a0 = fmaf(xv, gw[k],            a0);
        a1 = fmaf(xv, gw[DDIM + k],     a1);
        a2 = fmaf(xv, gw[2 * DDIM + k], a2);
        a3 = fmaf(xv, gw[3 * DDIM + k], a3);
    }
#pragma unroll
    for (int o = 16; o; o >>= 1) {
        a0 += __shfl_xor_sync(0xffffffffu, a0, o);
        a1 += __shfl_xor_sync(0xffffffffu, a1, o);
        a2 += __shfl_xor_sync(0xffffffffu, a2, o);
        a3 += __shfl_xor_sync(0xffffffffu, a3, o);
    }
    if (lane == 0) {
        float l[4] = {a0, a1, a2, a3};
        int i0 = 0;
#pragma unroll
        for (int e = 1; e < 4; e++) if (l[e] > l[i0]) i0 = e;
        int i1 = (i0 == 0) ? 1 : 0;
#pragma unroll
        for (int e = 0; e < 4; e++) if (e != i0 && l[e] > l[i1]) i1 = e;

        // softmax -> top2 -> renorm  ==  w0 = 1/(1+exp(l1-l0)) with l1<=l0
        float w0 = 1.0f / (1.0f + expf(l[i1] - l[i0]));
        float w1 = 1.0f - w0;

        int s0 = atomicAdd(&g_cnt[i0], 1);
        g_tok[i0][s0] = warp;  g_wgt[i0][s0] = w0;
        int s1 = atomicAdd(&g_cnt[i1], 1);
        g_tok[i1][s1] = warp;  g_wgt[i1][s1] = w1;
    }
}

// ---------------------------------------------------------------------------
// GEMM1: h1[e][m][n] = gelu( sum_k x[tok[e][m]][k] * w1[e][k][n] + b1[e][n] )
// 128x128 tile, BK=8, 256 threads, 8x8 per-thread microtile. A rows gathered
// through the token list. One launch over all 4 experts (disjoint h1 regions).
// ---------------------------------------------------------------------------
__global__ void __launch_bounds__(256)
gemm1_kernel(const float* __restrict__ x,
             const float* __restrict__ w1,
             const float* __restrict__ b1) {
    int e   = blockIdx.z;
    int cnt = g_cnt[e];
    int m0  = blockIdx.y * BM;
    if (m0 >= cnt) return;
    int n0  = blockIdx.x * BN;

    const float* Bp = w1 + (size_t)e * DDIM * HDIM;
    float*       Cp = g_h1 + (size_t)e * NTOK * HDIM;

    __shared__ float As[BK][BM];
    __shared__ float Bs[BK][BN];

    int t    = threadIdx.x;
    int arow = t >> 1, acol = (t & 1) * 4;   // A tile load map (pairs share row)
    int brow = t >> 5, bcol = (t & 31) * 4;  // B tile load map (coalesced)
    int ty   = t >> 4, tx = t & 15;

    int slot = m0 + arow; if (slot > cnt - 1) slot = cnt - 1;
    const float* Arow = x + (size_t)g_tok[e][slot] * DDIM;

    float acc[8][8];
#pragma unroll
    for (int i = 0; i < 8; i++)
#pragma unroll
        for (int j = 0; j < 8; j++) acc[i][j] = 0.f;

    for (int k0 = 0; k0 < DDIM; k0 += BK) {
        float4 av = *(const float4*)(Arow + k0 + acol);
        float4 bv = *(const float4*)(Bp + (size_t)(k0 + brow) * HDIM + n0 + bcol);
        As[acol + 0][arow] = av.x;
        As[acol + 1][arow] = av.y;
        As[acol + 2][arow] = av.z;
        As[acol + 3][arow] = av.w;
        *(float4*)&Bs[brow][bcol] = bv;
        __syncthreads();
#pragma unroll
        for (int kk = 0; kk < BK; kk++) {
            float4 aA = *(const float4*)&As[kk][ty * 8];
            float4 aB = *(const float4*)&As[kk][ty * 8 + 4];
            float4 bA = *(const float4*)&Bs[kk][tx * 8];
            float4 bB = *(const float4*)&Bs[kk][tx * 8 + 4];
            float a[8] = {aA.x, aA.y, aA.z, aA.w, aB.x, aB.y, aB.z, aB.w};
            float b[8] = {bA.x, bA.y, bA.z, bA.w, bB.x, bB.y, bB.z, bB.w};
#pragma unroll
            for (int i = 0; i < 8; i++)
#pragma unroll
                for (int j = 0; j < 8; j++)
                    acc[i][j] = fmaf(a[i], b[j], acc[i][j]);
        }
        __syncthreads();
    }

#pragma unroll
    for (int i = 0; i < 8; i++) {
        int m = m0 + ty * 8 + i;
        if (m < cnt) {
            float* crow = Cp + (size_t)m * HDIM + n0 + tx * 8;
            const float* brow_b = b1 + (size_t)e * HDIM + n0 + tx * 8;
#pragma unroll
            for (int j = 0; j < 8; j++) {
                float v = acc[i][j] + brow_b[j];
                crow[j] = 0.5f * v * (1.0f + erff(v * 0.70710678118654752f));
            }
        }
    }
}

// ---------------------------------------------------------------------------
// GEMM2: out[tok][n] += wgt * ( sum_k h1[e][m][k] * w2[e][k][n] + b2[e][n] )
// Launched once per expert (sequential) so the += scatter never races.
// ---------------------------------------------------------------------------
__global__ void __launch_bounds__(256)
gemm2_kernel(int e,
             const float* __restrict__ w2,
             const float* __restrict__ b2,
             float* __restrict__ out) {
    int cnt = g_cnt[e];
    int m0  = blockIdx.y * BM;
    if (m0 >= cnt) return;
    int n0  = blockIdx.x * BN;

    const float* Ap = g_h1 + (size_t)e * NTOK * HDIM;
    const float* Bp = w2 + (size_t)e * HDIM * HDIM;

    __shared__ float As[BK][BM];
    __shared__ float Bs[BK][BN];

    int t    = threadIdx.x;
    int arow = t >> 1, acol = (t & 1) * 4;
    int brow = t >> 5, bcol = (t & 31) * 4;
    int ty   = t >> 4, tx = t & 15;

    int slot = m0 + arow; if (slot > cnt - 1) slot = cnt - 1;
    const float* Arow = Ap + (size_t)slot * HDIM;

    float acc[8][8];
#pragma unroll
    for (int i = 0; i < 8; i++)
#pragma unroll
        for (int j = 0; j < 8; j++) acc[i][j] = 0.f;

    for (int k0 = 0; k0 < HDIM; k0 += BK) {
        float4 av = *(const float4*)(Arow + k0 + acol);
        float4 bv = *(const float4*)(Bp + (size_t)(k0 + brow) * HDIM + n0 + bcol);
        As[acol + 0][arow] = av.x;
        As[acol + 1][arow] = av.y;
        As[acol + 2][arow] = av.z;
        As[acol + 3][arow] = av.w;
        *(float4*)&Bs[brow][bcol] = bv;
        __syncthreads();
#pragma unroll
        for (int kk = 0; kk < BK; kk++) {
            float4 aA = *(const float4*)&As[kk][ty * 8];
            float4 aB = *(const float4*)&As[kk][ty * 8 + 4];
            float4 bA = *(const float4*)&Bs[kk][tx * 8];
            float4 bB = *(const float4*)&Bs[kk][tx * 8 + 4];
            float a[8] = {aA.x, aA.y, aA.z, aA.w, aB.x, aB.y, aB.z, aB.w};
            float b[8] = {bA.x, bA.y, bA.z, bA.w, bB.x, bB.y, bB.z, bB.w};
#pragma unroll
            for (int i = 0; i < 8; i++)
#pragma unroll
                for (int j = 0; j < 8; j++)
                    acc[i][j] = fmaf(a[i], b[j], acc[i][j]);
        }
        __syncthreads();
    }

#pragma unroll
    for (int i = 0; i < 8; i++) {
        int m = m0 + ty * 8 + i;
        if (m < cnt) {
            int   tok = g_tok[e][m];
            float w   = g_wgt[e][m];
            float* orow = out + (size_t)tok * HDIM + n0 + tx * 8;
            const float* brow_b = b2 + (size_t)e * HDIM + n0 + tx * 8;
#pragma unroll
            for (int j = 0; j < 8; j++)
                orow[j] += w * (acc[i][j] + brow_b[j]);
        }
    }
}

// ---------------------------------------------------------------------------
extern "C" void kernel_launch(void* const* d_in, const int* in_sizes, int n_in,
                              void* d_out, int out_size) {
    const float* x  = (const float*)d_in[0];  // hidden_states [B,S,D]
    const float* gw = (const float*)d_in[1];  // gate_w [E,D]
    const float* w1 = (const float*)d_in[2];  // [E,D,H]
    const float* b1 = (const float*)d_in[3];  // [E,H]
    const float* w2 = (const float*)d_in[4];  // [E,H,H]
    const float* b2 = (const float*)d_in[5];  // [E,H]
    float* out = (float*)d_out;               // [B,S,H] fp32

    zero_kernel<<<2048, 256>>>((float4*)out, (long)out_size / 4);
    router_kernel<<<NTOK / 8, 256>>>(x, gw);
    gemm1_kernel<<<dim3(HDIM / BN, NTOK / BM, NEXP), 256>>>(x, w1, b1);
    for (int e = 0; e < NEXP; e++)
        gemm2_kernel<<<dim3(HDIM / BN, NTOK / BM), 256>>>(e, w2, b2, out);
}

// round 3
// speedup vs baseline: 2.9369x; 2.9369x over previous
#include <cuda_runtime.h>
#include <cuda_bf16.h>
#include <math.h>
#include <stdint.h>

// Problem constants (B=8, S=2048, D=2048, H=2048, E=4, TOP_K=2)
#define NTOK 16384
#define DDIM 2048
#define HDIM 2048
#define NEXP 4
#define NCH  32              // K / 64 chunks

// Tile config
#define BM 128
#define BN 128
#define BK 64                // bf16 elems per K-chunk (128 bytes/row)
#define TILE_BYTES (128 * 128)          // one 128-row x 128B operand tile
#define BUF_BYTES  (4 * TILE_BYTES)     // Ah | Al | Bh | Bl
#define SMEM_TOTAL (1024 + 2 * BUF_BYTES)

// ---------------------------------------------------------------------------
// Scratch (static device arrays — no runtime allocation)
// ---------------------------------------------------------------------------
__device__ int   g_cnt[NEXP];
__device__ int   g_tok[NEXP][NTOK];
__device__ float g_wgt[NEXP][NTOK];

__device__ __nv_bfloat16 g_xh[(size_t)NTOK * DDIM];
__device__ __nv_bfloat16 g_xl[(size_t)NTOK * DDIM];
__device__ __nv_bfloat16 g_w1h[(size_t)NEXP * HDIM * DDIM];  // [e][n][k]
__device__ __nv_bfloat16 g_w1l[(size_t)NEXP * HDIM * DDIM];
__device__ __nv_bfloat16 g_w2h[(size_t)NEXP * HDIM * HDIM];  // [e][n][k]
__device__ __nv_bfloat16 g_w2l[(size_t)NEXP * HDIM * HDIM];
__device__ __nv_bfloat16 g_h1h[(size_t)NEXP * NTOK * HDIM];  // [e][slot][k]
__device__ __nv_bfloat16 g_h1l[(size_t)NEXP * NTOK * HDIM];

// ---------------------------------------------------------------------------
// Helpers
// ---------------------------------------------------------------------------
__device__ __forceinline__ uint32_t smem_u32(const void* p) {
    uint32_t a;
    asm("{ .reg .u64 t; cvta.to.shared.u64 t, %1; cvt.u32.u64 %0, t; }"
        : "=r"(a) : "l"(p));
    return a;
}
// SW128-style XOR swizzle: 128B rows, 16B chunks; chunk ^= (row & 7)
__device__ __forceinline__ uint32_t swz(uint32_t row, uint32_t byteoff) {
    uint32_t c16 = byteoff >> 4, lo = byteoff & 15;
    return row * 128 + (((c16 ^ (row & 7)) & 7) << 4) + lo;
}
__device__ __forceinline__ uint32_t lds32(uint32_t addr) {
    uint32_t v;
    asm volatile("ld.shared.b32 %0, [%1];" : "=r"(v) : "r"(addr));
    return v;
}
__device__ __forceinline__ void cp16(uint32_t saddr, const void* gaddr) {
    asm volatile("cp.async.cg.shared.global [%0], [%1], 16;" :: "r"(saddr), "l"(gaddr));
}
#define CP_COMMIT() asm volatile("cp.async.commit_group;" ::: "memory")
#define CP_WAIT0()  asm volatile("cp.async.wait_group 0;" ::: "memory")

__device__ __forceinline__ void mma16816(float* d, const uint32_t* a, const uint32_t* b) {
    asm volatile(
        "mma.sync.aligned.m16n8k16.row.col.f32.bf16.bf16.f32 "
        "{%0,%1,%2,%3}, {%4,%5,%6,%7}, {%8,%9}, {%0,%1,%2,%3};"
        : "+f"(d[0]), "+f"(d[1]), "+f"(d[2]), "+f"(d[3])
        : "r"(a[0]), "r"(a[1]), "r"(a[2]), "r"(a[3]), "r"(b[0]), "r"(b[1]));
}

// ---------------------------------------------------------------------------
__global__ void zero_kernel(float4* __restrict__ out, long n4) {
    long i = (long)blockIdx.x * blockDim.x + threadIdx.x;
    long st = (long)gridDim.x * blockDim.x;
    float4 z = make_float4(0.f, 0.f, 0.f, 0.f);
    for (; i < n4; i += st) out[i] = z;
    if (blockIdx.x == 0 && threadIdx.x < NEXP) g_cnt[threadIdx.x] = 0;
}

// x fp32 -> bf16 hi/lo
__global__ void convert_x(const float4* __restrict__ x4, long n4) {
    long i = (long)blockIdx.x * blockDim.x + threadIdx.x;
    long st = (long)gridDim.x * blockDim.x;
    __nv_bfloat162* xh2 = (__nv_bfloat162*)g_xh;
    __nv_bfloat162* xl2 = (__nv_bfloat162*)g_xl;
    for (; i < n4; i += st) {
        float4 v = x4[i];
        __nv_bfloat16 h0 = __float2bfloat16(v.x), h1 = __float2bfloat16(v.y);
        __nv_bfloat16 h2 = __float2bfloat16(v.z), h3 = __float2bfloat16(v.w);
        __nv_bfloat16 l0 = __float2bfloat16(v.x - __bfloat162float(h0));
        __nv_bfloat16 l1 = __float2bfloat16(v.y - __bfloat162float(h1));
        __nv_bfloat16 l2 = __float2bfloat16(v.z - __bfloat162float(h2));
        __nv_bfloat16 l3 = __float2bfloat16(v.w - __bfloat162float(h3));
        xh2[2 * i]     = __nv_bfloat162(h0, h1);
        xh2[2 * i + 1] = __nv_bfloat162(h2, h3);
        xl2[2 * i]     = __nv_bfloat162(l0, l1);
        xl2[2 * i + 1] = __nv_bfloat162(l2, l3);
    }
}

// w [E][K][N] fp32 -> wt [E][N][K] bf16 hi/lo (K = N = 2048)
__global__ void transpose_w(const float* __restrict__ w, int which) {
    __shared__ float tile[32][33];
    int e = blockIdx.z;
    int n0 = blockIdx.x * 32, k0 = blockIdx.y * 32;
    const float* src = w + (size_t)e * DDIM * HDIM;
    int tx = threadIdx.x, ty = threadIdx.y;
#pragma unroll
    for (int i = 0; i < 4; i++) {
        int k = k0 + ty + i * 8;
        tile[ty + i * 8][tx] = src[(size_t)k * HDIM + n0 + tx];
    }
    __syncthreads();
    __nv_bfloat16* oh = which ? g_w2h : g_w1h;
    __nv_bfloat16* ol = which ? g_w2l : g_w1l;
#pragma unroll
    for (int i = 0; i < 4; i++) {
        int n = n0 + ty + i * 8;
        float v = tile[tx][ty + i * 8];
        __nv_bfloat16 h = __float2bfloat16(v);
        __nv_bfloat16 l = __float2bfloat16(v - __bfloat162float(h));
        size_t o = ((size_t)e * HDIM + n) * DDIM + k0 + tx;
        oh[o] = h; ol[o] = l;
    }
}

// ---------------------------------------------------------------------------
// Router
// ---------------------------------------------------------------------------
__global__ void router_kernel(const float* __restrict__ x,
                              const float* __restrict__ gw) {
    int warp = (blockIdx.x * blockDim.x + threadIdx.x) >> 5;
    int lane = threadIdx.x & 31;
    if (warp >= NTOK) return;
    const float* xr = x + (size_t)warp * DDIM;
    float a0 = 0.f, a1 = 0.f, a2 = 0.f, a3 = 0.f;
    for (int k = lane; k < DDIM; k += 32) {
        float xv = xr[k];
        a0 = fmaf(xv, gw[k], a0);
        a1 = fmaf(xv, gw[DDIM + k], a1);
        a2 = fmaf(xv, gw[2 * DDIM + k], a2);
        a3 = fmaf(xv, gw[3 * DDIM + k], a3);
    }
#pragma unroll
    for (int o = 16; o; o >>= 1) {
        a0 += __shfl_xor_sync(0xffffffffu, a0, o);
        a1 += __shfl_xor_sync(0xffffffffu, a1, o);
        a2 += __shfl_xor_sync(0xffffffffu, a2, o);
        a3 += __shfl_xor_sync(0xffffffffu, a3, o);
    }
    if (lane == 0) {
        float l[4] = {a0, a1, a2, a3};
        int i0 = 0;
#pragma unroll
        for (int e = 1; e < 4; e++) if (l[e] > l[i0]) i0 = e;
        int i1 = (i0 == 0) ? 1 : 0;
#pragma unroll
        for (int e = 0; e < 4; e++) if (e != i0 && l[e] > l[i1]) i1 = e;
        float w0 = 1.0f / (1.0f + expf(l[i1] - l[i0]));
        float w1 = 1.0f - w0;
        int s0 = atomicAdd(&g_cnt[i0], 1);
        g_tok[i0][s0] = warp; g_wgt[i0][s0] = w0;
        int s1 = atomicAdd(&g_cnt[i1], 1);
        g_tok[i1][s1] = warp; g_wgt[i1][s1] = w1;
    }
}

// ---------------------------------------------------------------------------
// Shared GEMM core pieces (bf16x3, mma.sync m16n8k16)
// 8 warps: wm = wid&1 (2 x 64 rows), wn = wid>>1 (4 x 32 cols)
// ---------------------------------------------------------------------------
struct Frags {
    uint32_t ah[4][4], al[4][4];  // 4 m-tiles
    uint32_t bh[4][2], bl[4][2];  // 4 n-tiles
};

__device__ __forceinline__ void compute_chunk(uint32_t ab, uint32_t bufb,
                                              int wm, int wn, int g, int tig,
                                              float acc[4][4][4]) {
    uint32_t aBase = ab + bufb;                     // Ah
    uint32_t alB   = aBase + TILE_BYTES;            // Al
    uint32_t bBase = aBase + 2 * TILE_BYTES;        // Bh
    uint32_t blB   = aBase + 3 * TILE_BYTES;        // Bl
#pragma unroll
    for (int s = 0; s < 4; s++) {
        Frags f;
        uint32_t boff = s * 32 + tig * 4;
#pragma unroll
        for (int mt = 0; mt < 4; mt++) {
            uint32_t r0 = wm * 64 + mt * 16 + g;
            uint32_t r1 = r0 + 8;
            f.ah[mt][0] = lds32(aBase + swz(r0, boff));
            f.ah[mt][1] = lds32(aBase + swz(r1, boff));
            f.ah[mt][2] = lds32(aBase + swz(r0, boff + 16));
            f.ah[mt][3] = lds32(aBase + swz(r1, boff + 16));
            f.al[mt][0] = lds32(alB + swz(r0, boff));
            f.al[mt][1] = lds32(alB + swz(r1, boff));
            f.al[mt][2] = lds32(alB + swz(r0, boff + 16));
            f.al[mt][3] = lds32(alB + swz(r1, boff + 16));
        }
#pragma unroll
        for (int nt = 0; nt < 4; nt++) {
            uint32_t nr = wn * 32 + nt * 8 + g;
            f.bh[nt][0] = lds32(bBase + swz(nr, boff));
            f.bh[nt][1] = lds32(bBase + swz(nr, boff + 16));
            f.bl[nt][0] = lds32(blB + swz(nr, boff));
            f.bl[nt][1] = lds32(blB + swz(nr, boff + 16));
        }
        // three-term split product
#pragma unroll
        for (int mt = 0; mt < 4; mt++)
#pragma unroll
            for (int nt = 0; nt < 4; nt++)
                mma16816(acc[mt][nt], f.ah[mt], f.bh[nt]);
#pragma unroll
        for (int mt = 0; mt < 4; mt++)
#pragma unroll
            for (int nt = 0; nt < 4; nt++)
                mma16816(acc[mt][nt], f.ah[mt], f.bl[nt]);
#pragma unroll
        for (int mt = 0; mt < 4; mt++)
#pragma unroll
            for (int nt = 0; nt < 4; nt++)
                mma16816(acc[mt][nt], f.al[mt], f.bh[nt]);
    }
}

// ---------------------------------------------------------------------------
// GEMM1: h1[e][m][:] = gelu(x[tok] @ w1[e]^T-layout + b1[e]) -> bf16 hi/lo
// ---------------------------------------------------------------------------
__global__ void __launch_bounds__(256, 1)
moe_gemm1(const float* __restrict__ b1) {
    int e = blockIdx.z;
    int cnt = g_cnt[e];
    int m0 = blockIdx.y * BM;
    if (m0 >= cnt) return;
    int n0 = blockIdx.x * BN;

    __shared__ int s_tok[BM];
    extern __shared__ char dynsm[];
    uint32_t ab = (smem_u32(dynsm) + 1023) & ~1023u;

    int tid = threadIdx.x;
    int wid = tid >> 5, lane = tid & 31;
    int wm = wid & 1, wn = wid >> 1;
    int g = lane >> 2, tig = lane & 3;

    if (tid < BM) {
        int s = m0 + tid; if (s > cnt - 1) s = cnt - 1;
        s_tok[tid] = g_tok[e][s];
    }
    __syncthreads();

    const __nv_bfloat16* wh = g_w1h + (size_t)e * HDIM * DDIM;
    const __nv_bfloat16* wl = g_w1l + (size_t)e * HDIM * DDIM;

    float acc[4][4][4];
#pragma unroll
    for (int i = 0; i < 4; i++)
#pragma unroll
        for (int j = 0; j < 4; j++)
#pragma unroll
            for (int k = 0; k < 4; k++) acc[i][j][k] = 0.f;

    // async tile loader
    auto load_chunk = [&](int c, uint32_t bufb) {
        int k0 = c * BK;
#pragma unroll
        for (int i = 0; i < 4; i++) {
            int id = tid + i * 256;
            int r = id >> 3, c16 = id & 7;
            uint32_t so = swz((uint32_t)r, (uint32_t)(c16 * 16));
            size_t go = (size_t)s_tok[r] * DDIM + k0 + c16 * 8;
            cp16(ab + bufb + so, g_xh + go);
            cp16(ab + bufb + TILE_BYTES + so, g_xl + go);
            size_t gb = (size_t)(n0 + r) * DDIM + k0 + c16 * 8;
            cp16(ab + bufb + 2 * TILE_BYTES + so, wh + gb);
            cp16(ab + bufb + 3 * TILE_BYTES + so, wl + gb);
        }
        CP_COMMIT();
    };

    load_chunk(0, 0);
    for (int c = 0; c < NCH; c++) {
        CP_WAIT0();
        __syncthreads();
        if (c + 1 < NCH) load_chunk(c + 1, (uint32_t)((c + 1) & 1) * BUF_BYTES);
        compute_chunk(ab, (uint32_t)(c & 1) * BUF_BYTES, wm, wn, g, tig, acc);
        __syncthreads();
    }

    // Epilogue: bias + exact GELU -> bf16 hi/lo -> global
    __nv_bfloat16* h1h = g_h1h + (size_t)e * NTOK * HDIM;
    __nv_bfloat16* h1l = g_h1l + (size_t)e * NTOK * HDIM;
    const float* bias = b1 + (size_t)e * HDIM;
#pragma unroll
    for (int nt = 0; nt < 4; nt++) {
        int n = n0 + wn * 32 + nt * 8 + tig * 2;
        float bv0 = bias[n], bv1 = bias[n + 1];
#pragma unroll
        for (int mt = 0; mt < 4; mt++) {
#pragma unroll
            for (int half = 0; half < 2; half++) {
                int m = m0 + wm * 64 + mt * 16 + g + half * 8;
                if (m < cnt) {
                    float v0 = acc[mt][nt][half * 2 + 0] + bv0;
                    float v1 = acc[mt][nt][half * 2 + 1] + bv1;
                    float g0 = 0.5f * v0 * (1.0f + erff(v0 * 0.70710678118654752f));
                    float g1 = 0.5f * v1 * (1.0f + erff(v1 * 0.70710678118654752f));
                    __nv_bfloat16 h0 = __float2bfloat16(g0);
                    __nv_bfloat16 h1 = __float2bfloat16(g1);
                    __nv_bfloat16 l0 = __float2bfloat16(g0 - __bfloat162float(h0));
                    __nv_bfloat16 l1 = __float2bfloat16(g1 - __bfloat162float(h1));
                    uint32_t hp = (uint32_t)__bfloat16_as_ushort(h0) |
                                  ((uint32_t)__bfloat16_as_ushort(h1) << 16);
                    uint32_t lp = (uint32_t)__bfloat16_as_ushort(l0) |
                                  ((uint32_t)__bfloat16_as_ushort(l1) << 16);
                    *(uint32_t*)(h1h + (size_t)m * HDIM + n) = hp;
                    *(uint32_t*)(h1l + (size_t)m * HDIM + n) = lp;
                }
            }
        }
    }
}

// ---------------------------------------------------------------------------
// GEMM2: out[tok][:] += wgt * (h1[e] @ w2[e] + b2[e])  (per-expert launch)
// ---------------------------------------------------------------------------
__global__ void __launch_bounds__(256, 1)
moe_gemm2(int e, const float* __restrict__ b2, float* __restrict__ out) {
    int cnt = g_cnt[e];
    int m0 = blockIdx.y * BM;
    if (m0 >= cnt) return;
    int n0 = blockIdx.x * BN;

    __shared__ int   s_tok[BM];
    __shared__ float s_wgt[BM];
    extern __shared__ char dynsm[];
    uint32_t ab = (smem_u32(dynsm) + 1023) & ~1023u;

    int tid = threadIdx.x;
    int wid = tid >> 5, lane = tid & 31;
    int wm = wid & 1, wn = wid >> 1;
    int g = lane >> 2, tig = lane & 3;

    if (tid < BM) {
        int s = m0 + tid; if (s > cnt - 1) s = cnt - 1;
        s_tok[tid] = g_tok[e][s];
        s_wgt[tid] = g_wgt[e][s];
    }
    __syncthreads();

    const __nv_bfloat16* ah = g_h1h + (size_t)e * NTOK * HDIM;
    const __nv_bfloat16* al = g_h1l + (size_t)e * NTOK * HDIM;
    const __nv_bfloat16* wh = g_w2h + (size_t)e * HDIM * HDIM;
    const __nv_bfloat16* wl = g_w2l + (size_t)e * HDIM * HDIM;

    float acc[4][4][4];
#pragma unroll
    for (int i = 0; i < 4; i++)
#pragma unroll
        for (int j = 0; j < 4; j++)
#pragma unroll
            for (int k = 0; k < 4; k++) acc[i][j][k] = 0.f;

    auto load_chunk = [&](int c, uint32_t bufb) {
        int k0 = c * BK;
#pragma unroll
        for (int i = 0; i < 4; i++) {
            int id = tid + i * 256;
            int r = id >> 3, c16 = id & 7;
            uint32_t so = swz((uint32_t)r, (uint32_t)(c16 * 16));
            int mm = m0 + r; if (mm > cnt - 1) mm = cnt - 1;
            size_t go = (size_t)mm * HDIM + k0 + c16 * 8;
            cp16(ab + bufb + so, ah + go);
            cp16(ab + bufb + TILE_BYTES + so, al + go);
            size_t gb = (size_t)(n0 + r) * HDIM + k0 + c16 * 8;
            cp16(ab + bufb + 2 * TILE_BYTES + so, wh + gb);
            cp16(ab + bufb + 3 * TILE_BYTES + so, wl + gb);
        }
        CP_COMMIT();
    };

    load_chunk(0, 0);
    for (int c = 0; c < NCH; c++) {
        CP_WAIT0();
        __syncthreads();
        if (c + 1 < NCH) load_chunk(c + 1, (uint32_t)((c + 1) & 1) * BUF_BYTES);
        compute_chunk(ab, (uint32_t)(c & 1) * BUF_BYTES, wm, wn, g, tig, acc);
        __syncthreads();
    }

    // Epilogue: (acc + b2) * wgt scattered += into out
    const float* bias = b2 + (size_t)e * HDIM;
#pragma unroll
    for (int nt = 0; nt < 4; nt++) {
        int n = n0 + wn * 32 + nt * 8 + tig * 2;
        float bv0 = bias[n], bv1 = bias[n + 1];
#pragma unroll
        for (int mt = 0; mt < 4; mt++) {
#pragma unroll
            for (int half = 0; half < 2; half++) {
                int rl = wm * 64 + mt * 16 + g + half * 8;
                int m = m0 + rl;
                if (m < cnt) {
                    float w = s_wgt[rl];
                    float* dst = out + (size_t)s_tok[rl] * HDIM + n;
                    dst[0] += w * (acc[mt][nt][half * 2 + 0] + bv0);
                    dst[1] += w * (acc[mt][nt][half * 2 + 1] + bv1);
                }
            }
        }
    }
}

// ---------------------------------------------------------------------------
extern "C" void kernel_launch(void* const* d_in, const int* in_sizes, int n_in,
                              void* d_out, int out_size) {
    const float* x  = (const float*)d_in[0];
    const float* gw = (const float*)d_in[1];
    const float* w1 = (const float*)d_in[2];
    const float* b1 = (const float*)d_in[3];
    const float* w2 = (const float*)d_in[4];
    const float* b2 = (const float*)d_in[5];
    float* out = (float*)d_out;

    cudaFuncSetAttribute(moe_gemm1, cudaFuncAttributeMaxDynamicSharedMemorySize, SMEM_TOTAL);
    cudaFuncSetAttribute(moe_gemm2, cudaFuncAttributeMaxDynamicSharedMemorySize, SMEM_TOTAL);

    zero_kernel<<<2048, 256>>>((float4*)out, (long)out_size / 4);
    convert_x<<<2048, 256>>>((const float4*)x, (long)NTOK * DDIM / 4);
    transpose_w<<<dim3(64, 64, 4), dim3(32, 8)>>>(w1, 0);
    transpose_w<<<dim3(64, 64, 4), dim3(32, 8)>>>(w2, 1);
    router_kernel<<<NTOK / 8, 256>>>(x, gw);

    moe_gemm1<<<dim3(HDIM / BN, NTOK / BM, NEXP), 256, SMEM_TOTAL>>>(b1);
    for (int e = 0; e < NEXP; e++)
        moe_gemm2<<<dim3(HDIM / BN, NTOK / BM), 256, SMEM_TOTAL>>>(e, b2, out);
}

// round 4
// speedup vs baseline: 3.0133x; 1.0260x over previous
#include <cuda_runtime.h>
#include <cuda_bf16.h>
#include <math.h>
#include <stdint.h>

// Problem constants (B=8, S=2048, D=2048, H=2048, E=4, TOP_K=2)
#define NTOK 16384
#define DDIM 2048
#define HDIM 2048
#define NEXP 4
#define NCH  32              // K / 64 chunks

// Tile config
#define BM 128
#define BN 128
#define BK 64                // bf16 elems per K-chunk (128 bytes/row)
#define TILE_BYTES (128 * 128)          // one 128-row x 128B operand tile
#define BUF_BYTES  (4 * TILE_BYTES)     // Ah | Al | Bh | Bl
#define NSTAGE 3
#define SMEM_TOTAL (1024 + NSTAGE * BUF_BYTES)

// ---------------------------------------------------------------------------
// Scratch (static device arrays — no runtime allocation)
// ---------------------------------------------------------------------------
__device__ int   g_cnt[NEXP];
__device__ int   g_tok[NEXP][NTOK];
__device__ float g_wgt[NEXP][NTOK];

__device__ __nv_bfloat16 g_xh[(size_t)NTOK * DDIM];
__device__ __nv_bfloat16 g_xl[(size_t)NTOK * DDIM];
__device__ __nv_bfloat16 g_w1h[(size_t)NEXP * HDIM * DDIM];  // [e][n][k]
__device__ __nv_bfloat16 g_w1l[(size_t)NEXP * HDIM * DDIM];
__device__ __nv_bfloat16 g_w2h[(size_t)NEXP * HDIM * HDIM];  // [e][n][k]
__device__ __nv_bfloat16 g_w2l[(size_t)NEXP * HDIM * HDIM];
__device__ __nv_bfloat16 g_h1h[(size_t)NEXP * NTOK * HDIM];  // [e][slot][k]
__device__ __nv_bfloat16 g_h1l[(size_t)NEXP * NTOK * HDIM];

// ---------------------------------------------------------------------------
// Helpers
// ---------------------------------------------------------------------------
__device__ __forceinline__ uint32_t smem_u32(const void* p) {
    uint32_t a;
    asm("{ .reg .u64 t; cvta.to.shared.u64 t, %1; cvt.u32.u64 %0, t; }"
        : "=r"(a) : "l"(p));
    return a;
}
// SW128-style XOR swizzle: 128B rows, 16B chunks; chunk ^= (row & 7)
__device__ __forceinline__ uint32_t swz(uint32_t row, uint32_t byteoff) {
    uint32_t c16 = byteoff >> 4, lo = byteoff & 15;
    return row * 128 + (((c16 ^ (row & 7)) & 7) << 4) + lo;
}
__device__ __forceinline__ void cp16(uint32_t saddr, const void* gaddr) {
    asm volatile("cp.async.cg.shared.global [%0], [%1], 16;" :: "r"(saddr), "l"(gaddr));
}
#define CP_COMMIT() asm volatile("cp.async.commit_group;" ::: "memory")
#define CP_WAIT0()  asm volatile("cp.async.wait_group 0;" ::: "memory")
#define CP_WAIT1()  asm volatile("cp.async.wait_group 1;" ::: "memory")

__device__ __forceinline__ void ldsm_x4(uint32_t* r, uint32_t addr) {
    asm volatile("ldmatrix.sync.aligned.m8n8.x4.shared.b16 {%0,%1,%2,%3}, [%4];"
        : "=r"(r[0]), "=r"(r[1]), "=r"(r[2]), "=r"(r[3]) : "r"(addr));
}
__device__ __forceinline__ void mma16816(float* d, const uint32_t* a, const uint32_t* b) {
    asm volatile(
        "mma.sync.aligned.m16n8k16.row.col.f32.bf16.bf16.f32 "
        "{%0,%1,%2,%3}, {%4,%5,%6,%7}, {%8,%9}, {%0,%1,%2,%3};"
        : "+f"(d[0]), "+f"(d[1]), "+f"(d[2]), "+f"(d[3])
        : "r"(a[0]), "r"(a[1]), "r"(a[2]), "r"(a[3]), "r"(b[0]), "r"(b[1]));
}

// ---------------------------------------------------------------------------
__global__ void zero_kernel(float4* __restrict__ out, long n4) {
    long i = (long)blockIdx.x * blockDim.x + threadIdx.x;
    long st = (long)gridDim.x * blockDim.x;
    float4 z = make_float4(0.f, 0.f, 0.f, 0.f);
    for (; i < n4; i += st) out[i] = z;
    if (blockIdx.x == 0 && threadIdx.x < NEXP) g_cnt[threadIdx.x] = 0;
}

// x fp32 -> bf16 hi/lo
__global__ void convert_x(const float4* __restrict__ x4, long n4) {
    long i = (long)blockIdx.x * blockDim.x + threadIdx.x;
    long st = (long)gridDim.x * blockDim.x;
    __nv_bfloat162* xh2 = (__nv_bfloat162*)g_xh;
    __nv_bfloat162* xl2 = (__nv_bfloat162*)g_xl;
    for (; i < n4; i += st) {
        float4 v = x4[i];
        __nv_bfloat16 h0 = __float2bfloat16(v.x), h1 = __float2bfloat16(v.y);
        __nv_bfloat16 h2 = __float2bfloat16(v.z), h3 = __float2bfloat16(v.w);
        __nv_bfloat16 l0 = __float2bfloat16(v.x - __bfloat162float(h0));
        __nv_bfloat16 l1 = __float2bfloat16(v.y - __bfloat162float(h1));
        __nv_bfloat16 l2 = __float2bfloat16(v.z - __bfloat162float(h2));
        __nv_bfloat16 l3 = __float2bfloat16(v.w - __bfloat162float(h3));
        xh2[2 * i]     = __nv_bfloat162(h0, h1);
        xh2[2 * i + 1] = __nv_bfloat162(h2, h3);
        xl2[2 * i]     = __nv_bfloat162(l0, l1);
        xl2[2 * i + 1] = __nv_bfloat162(l2, l3);
    }
}

// w [E][K][N] fp32 -> wt [E][N][K] bf16 hi/lo (K = N = 2048)
__global__ void transpose_w(const float* __restrict__ w, int which) {
    __shared__ float tile[32][33];
    int e = blockIdx.z;
    int n0 = blockIdx.x * 32, k0 = blockIdx.y * 32;
    const float* src = w + (size_t)e * DDIM * HDIM;
    int tx = threadIdx.x, ty = threadIdx.y;
#pragma unroll
    for (int i = 0; i < 4; i++) {
        int k = k0 + ty + i * 8;
        tile[ty + i * 8][tx] = src[(size_t)k * HDIM + n0 + tx];
    }
    __syncthreads();
    __nv_bfloat16* oh = which ? g_w2h : g_w1h;
    __nv_bfloat16* ol = which ? g_w2l : g_w1l;
#pragma unroll
    for (int i = 0; i < 4; i++) {
        int n = n0 + ty + i * 8;
        float v = tile[tx][ty + i * 8];
        __nv_bfloat16 h = __float2bfloat16(v);
        __nv_bfloat16 l = __float2bfloat16(v - __bfloat162float(h));
        size_t o = ((size_t)e * HDIM + n) * DDIM + k0 + tx;
        oh[o] = h; ol[o] = l;
    }
}

// ---------------------------------------------------------------------------
// Router
// ---------------------------------------------------------------------------
__global__ void router_kernel(const float* __restrict__ x,
                              const float* __restrict__ gw) {
    int warp = (blockIdx.x * blockDim.x + threadIdx.x) >> 5;
    int lane = threadIdx.x & 31;
    if (warp >= NTOK) return;
    const float* xr = x + (size_t)warp * DDIM;
    float a0 = 0.f, a1 = 0.f, a2 = 0.f, a3 = 0.f;
    for (int k = lane; k < DDIM; k += 32) {
        float xv = xr[k];
        a0 = fmaf(xv, gw[k], a0);
        a1 = fmaf(xv, gw[DDIM + k], a1);
        a2 = fmaf(xv, gw[2 * DDIM + k], a2);
        a3 = fmaf(xv, gw[3 * DDIM + k], a3);
    }
#pragma unroll
    for (int o = 16; o; o >>= 1) {
        a0 += __shfl_xor_sync(0xffffffffu, a0, o);
        a1 += __shfl_xor_sync(0xffffffffu, a1, o);
        a2 += __shfl_xor_sync(0xffffffffu, a2, o);
        a3 += __shfl_xor_sync(0xffffffffu, a3, o);
    }
    if (lane == 0) {
        float l[4] = {a0, a1, a2, a3};
        int i0 = 0;
#pragma unroll
        for (int e = 1; e < 4; e++) if (l[e] > l[i0]) i0 = e;
        int i1 = (i0 == 0) ? 1 : 0;
#pragma unroll
        for (int e = 0; e < 4; e++) if (e != i0 && l[e] > l[i1]) i1 = e;
        float w0 = 1.0f / (1.0f + expf(l[i1] - l[i0]));
        float w1 = 1.0f - w0;
        int s0 = atomicAdd(&g_cnt[i0], 1);
        g_tok[i0][s0] = warp; g_wgt[i0][s0] = w0;
        int s1 = atomicAdd(&g_cnt[i1], 1);
        g_tok[i1][s1] = warp; g_wgt[i1][s1] = w1;
    }
}

// ---------------------------------------------------------------------------
// GEMM core: bf16x3, mma.sync m16n8k16, ldmatrix fragment loads.
// 8 warps: wm = wid&1 (2 x 64 rows), wn = wid>>1 (4 x 32 cols)
// ---------------------------------------------------------------------------
__device__ __forceinline__ void compute_chunk(uint32_t base, int wm, int wn,
                                              int lane, float acc[4][4][4]) {
    uint32_t aH = base;
    uint32_t aL = base + TILE_BYTES;
    uint32_t bH = base + 2 * TILE_BYTES;
    uint32_t bL = base + 3 * TILE_BYTES;

    // per-lane ldmatrix row/col offsets (constant across s)
    uint32_t a_row = (uint32_t)(wm * 64) + (lane & 15);
    uint32_t a_kb  = (uint32_t)((lane >> 4) << 4);
    uint32_t b_row0 = (uint32_t)(wn * 32) + (((lane >> 4) & 1) << 3) + (lane & 7);
    uint32_t b_kb  = (uint32_t)(((lane >> 3) & 1) << 4);

#pragma unroll
    for (int s = 0; s < 4; s++) {
        uint32_t boff = s * 32;
        uint32_t ah[4][4], al[4][4], bh[4][2], bl[4][2];
#pragma unroll
        for (int mt = 0; mt < 4; mt++) {
            uint32_t off = swz(a_row + mt * 16, boff + a_kb);
            ldsm_x4(ah[mt], aH + off);
            ldsm_x4(al[mt], aL + off);
        }
#pragma unroll
        for (int p = 0; p < 2; p++) {
            uint32_t off = swz(b_row0 + p * 16, boff + b_kb);
            uint32_t rh[4], rl[4];
            ldsm_x4(rh, bH + off);
            ldsm_x4(rl, bL + off);
            bh[p * 2][0] = rh[0]; bh[p * 2][1] = rh[1];
            bh[p * 2 + 1][0] = rh[2]; bh[p * 2 + 1][1] = rh[3];
            bl[p * 2][0] = rl[0]; bl[p * 2][1] = rl[1];
            bl[p * 2 + 1][0] = rl[2]; bl[p * 2 + 1][1] = rl[3];
        }
#pragma unroll
        for (int mt = 0; mt < 4; mt++)
#pragma unroll
            for (int nt = 0; nt < 4; nt++)
                mma16816(acc[mt][nt], ah[mt], bh[nt]);
#pragma unroll
        for (int mt = 0; mt < 4; mt++)
#pragma unroll
            for (int nt = 0; nt < 4; nt++)
                mma16816(acc[mt][nt], ah[mt], bl[nt]);
#pragma unroll
        for (int mt = 0; mt < 4; mt++)
#pragma unroll
            for (int nt = 0; nt < 4; nt++)
                mma16816(acc[mt][nt], al[mt], bh[nt]);
    }
}

// ---------------------------------------------------------------------------
// GEMM1: h1[e][m][:] = gelu(x[tok] @ w1[e] + b1[e]) -> bf16 hi/lo
// ---------------------------------------------------------------------------
__global__ void __launch_bounds__(256, 1)
moe_gemm1(const float* __restrict__ b1) {
    int e = blockIdx.z;
    int cnt = g_cnt[e];
    int m0 = blockIdx.y * BM;
    if (m0 >= cnt) return;
    int n0 = blockIdx.x * BN;

    __shared__ int s_tok[BM];
    extern __shared__ char dynsm[];
    uint32_t ab = (smem_u32(dynsm) + 1023) & ~1023u;

    int tid = threadIdx.x;
    int wid = tid >> 5, lane = tid & 31;
    int wm = wid & 1, wn = wid >> 1;

    if (tid < BM) {
        int s = m0 + tid; if (s > cnt - 1) s = cnt - 1;
        s_tok[tid] = g_tok[e][s];
    }
    __syncthreads();

    const __nv_bfloat16* wh = g_w1h + (size_t)e * HDIM * DDIM;
    const __nv_bfloat16* wl = g_w1l + (size_t)e * HDIM * DDIM;

    float acc[4][4][4];
#pragma unroll
    for (int i = 0; i < 4; i++)
#pragma unroll
        for (int j = 0; j < 4; j++)
#pragma unroll
            for (int k = 0; k < 4; k++) acc[i][j][k] = 0.f;

    int r = tid >> 3, c16 = tid & 7;                  // 256 threads cover 128 rows x 2 chunks? no:
    // each thread loads 4 x 16B per operand tile: rows tid>>3 (+32 stride), chunk tid&7
    auto load_chunk = [&](int c, uint32_t bufb) {
        int k0 = c * BK;
#pragma unroll
        for (int i = 0; i < 4; i++) {
            int rr = r + i * 32;
            uint32_t so = swz((uint32_t)rr, (uint32_t)(c16 * 16));
            size_t go = (size_t)s_tok[rr] * DDIM + k0 + c16 * 8;
            cp16(ab + bufb + so, g_xh + go);
            cp16(ab + bufb + TILE_BYTES + so, g_xl + go);
            size_t gb = (size_t)(n0 + rr) * DDIM + k0 + c16 * 8;
            cp16(ab + bufb + 2 * TILE_BYTES + so, wh + gb);
            cp16(ab + bufb + 3 * TILE_BYTES + so, wl + gb);
        }
        CP_COMMIT();
    };

    load_chunk(0, 0);
    load_chunk(1, BUF_BYTES);
    for (int c = 0; c < NCH; c++) {
        if (c + 1 < NCH) CP_WAIT1(); else CP_WAIT0();
        __syncthreads();
        if (c + 2 < NCH) load_chunk(c + 2, (uint32_t)((c + 2) % NSTAGE) * BUF_BYTES);
        compute_chunk(ab + (uint32_t)(c % NSTAGE) * BUF_BYTES, wm, wn, lane, acc);
    }

    // Epilogue: bias + exact GELU -> bf16 hi/lo -> global
    int g = lane >> 2, tig = lane & 3;
    __nv_bfloat16* h1h = g_h1h + (size_t)e * NTOK * HDIM;
    __nv_bfloat16* h1l = g_h1l + (size_t)e * NTOK * HDIM;
    const float* bias = b1 + (size_t)e * HDIM;
#pragma unroll
    for (int nt = 0; nt < 4; nt++) {
        int n = n0 + wn * 32 + nt * 8 + tig * 2;
        float bv0 = bias[n], bv1 = bias[n + 1];
#pragma unroll
        for (int mt = 0; mt < 4; mt++) {
#pragma unroll
            for (int half = 0; half < 2; half++) {
                int m = m0 + wm * 64 + mt * 16 + g + half * 8;
                if (m < cnt) {
                    float v0 = acc[mt][nt][half * 2 + 0] + bv0;
                    float v1 = acc[mt][nt][half * 2 + 1] + bv1;
                    float g0 = 0.5f * v0 * (1.0f + erff(v0 * 0.70710678118654752f));
                    float g1 = 0.5f * v1 * (1.0f + erff(v1 * 0.70710678118654752f));
                    __nv_bfloat16 h0 = __float2bfloat16(g0);
                    __nv_bfloat16 h1 = __float2bfloat16(g1);
                    __nv_bfloat16 l0 = __float2bfloat16(g0 - __bfloat162float(h0));
                    __nv_bfloat16 l1 = __float2bfloat16(g1 - __bfloat162float(h1));
                    uint32_t hp = (uint32_t)__bfloat16_as_ushort(h0) |
                                  ((uint32_t)__bfloat16_as_ushort(h1) << 16);
                    uint32_t lp = (uint32_t)__bfloat16_as_ushort(l0) |
                                  ((uint32_t)__bfloat16_as_ushort(l1) << 16);
                    *(uint32_t*)(h1h + (size_t)m * HDIM + n) = hp;
                    *(uint32_t*)(h1l + (size_t)m * HDIM + n) = lp;
                }
            }
        }
    }
}

// ---------------------------------------------------------------------------
// GEMM2: out[tok][:] += wgt * (h1[e] @ w2[e] + b2[e])  (per-expert launch)
// ---------------------------------------------------------------------------
__global__ void __launch_bounds__(256, 1)
moe_gemm2(int e, const float* __restrict__ b2, float* __restrict__ out) {
    int cnt = g_cnt[e];
    int m0 = blockIdx.y * BM;
    if (m0 >= cnt) return;
    int n0 = blockIdx.x * BN;

    __shared__ int   s_tok[BM];
    __shared__ float s_wgt[BM];
    extern __shared__ char dynsm[];
    uint32_t ab = (smem_u32(dynsm) + 1023) & ~1023u;

    int tid = threadIdx.x;
    int wid = tid >> 5, lane = tid & 31;
    int wm = wid & 1, wn = wid >> 1;

    if (tid < BM) {
        int s = m0 + tid; if (s > cnt - 1) s = cnt - 1;
        s_tok[tid] = g_tok[e][s];
        s_wgt[tid] = g_wgt[e][s];
    }
    __syncthreads();

    const __nv_bfloat16* ah = g_h1h + (size_t)e * NTOK * HDIM;
    const __nv_bfloat16* al = g_h1l + (size_t)e * NTOK * HDIM;
    const __nv_bfloat16* wh = g_w2h + (size_t)e * HDIM * HDIM;
    const __nv_bfloat16* wl = g_w2l + (size_t)e * HDIM * HDIM;

    float acc[4][4][4];
#pragma unroll
    for (int i = 0; i < 4; i++)
#pragma unroll
        for (int j = 0; j < 4; j++)
#pragma unroll
            for (int k = 0; k < 4; k++) acc[i][j][k] = 0.f;

    int r = tid >> 3, c16 = tid & 7;
    auto load_chunk = [&](int c, uint32_t bufb) {
        int k0 = c * BK;
#pragma unroll
        for (int i = 0; i < 4; i++) {
            int rr = r + i * 32;
            uint32_t so = swz((uint32_t)rr, (uint32_t)(c16 * 16));
            int mm = m0 + rr; if (mm > cnt - 1) mm = cnt - 1;
            size_t go = (size_t)mm * HDIM + k0 + c16 * 8;
            cp16(ab + bufb + so, ah + go);
            cp16(ab + bufb + TILE_BYTES + so, al + go);
            size_t gb = (size_t)(n0 + rr) * HDIM + k0 + c16 * 8;
            cp16(ab + bufb + 2 * TILE_BYTES + so, wh + gb);
            cp16(ab + bufb + 3 * TILE_BYTES + so, wl + gb);
        }
        CP_COMMIT();
    };

    load_chunk(0, 0);
    load_chunk(1, BUF_BYTES);
    for (int c = 0; c < NCH; c++) {
        if (c + 1 < NCH) CP_WAIT1(); else CP_WAIT0();
        __syncthreads();
        if (c + 2 < NCH) load_chunk(c + 2, (uint32_t)((c + 2) % NSTAGE) * BUF_BYTES);
        compute_chunk(ab + (uint32_t)(c % NSTAGE) * BUF_BYTES, wm, wn, lane, acc);
    }

    // Epilogue: (acc + b2) * wgt scattered += into out
    int g = lane >> 2, tig = lane & 3;
    const float* bias = b2 + (size_t)e * HDIM;
#pragma unroll
    for (int nt = 0; nt < 4; nt++) {
        int n = n0 + wn * 32 + nt * 8 + tig * 2;
        float bv0 = bias[n], bv1 = bias[n + 1];
#pragma unroll
        for (int mt = 0; mt < 4; mt++) {
#pragma unroll
            for (int half = 0; half < 2; half++) {
                int rl = wm * 64 + mt * 16 + g + half * 8;
                int m = m0 + rl;
                if (m < cnt) {
                    float w = s_wgt[rl];
                    float* dst = out + (size_t)s_tok[rl] * HDIM + n;
                    dst[0] += w * (acc[mt][nt][half * 2 + 0] + bv0);
                    dst[1] += w * (acc[mt][nt][half * 2 + 1] + bv1);
                }
            }
        }
    }
}

// ---------------------------------------------------------------------------
extern "C" void kernel_launch(void* const* d_in, const int* in_sizes, int n_in,
                              void* d_out, int out_size) {
    const float* x  = (const float*)d_in[0];
    const float* gw = (const float*)d_in[1];
    const float* w1 = (const float*)d_in[2];
    const float* b1 = (const float*)d_in[3];
    const float* w2 = (const float*)d_in[4];
    const float* b2 = (const float*)d_in[5];
    float* out = (float*)d_out;

    cudaFuncSetAttribute(moe_gemm1, cudaFuncAttributeMaxDynamicSharedMemorySize, SMEM_TOTAL);
    cudaFuncSetAttribute(moe_gemm2, cudaFuncAttributeMaxDynamicSharedMemorySize, SMEM_TOTAL);

    zero_kernel<<<2048, 256>>>((float4*)out, (long)out_size / 4);
    convert_x<<<2048, 256>>>((const float4*)x, (long)NTOK * DDIM / 4);
    transpose_w<<<dim3(64, 64, 4), dim3(32, 8)>>>(w1, 0);
    transpose_w<<<dim3(64, 64, 4), dim3(32, 8)>>>(w2, 1);
    router_kernel<<<NTOK / 8, 256>>>(x, gw);

    moe_gemm1<<<dim3(HDIM / BN, NTOK / BM, NEXP), 256, SMEM_TOTAL>>>(b1);
    for (int e = 0; e < NEXP; e++)
        moe_gemm2<<<dim3(HDIM / BN, NTOK / BM), 256, SMEM_TOTAL>>>(e, b2, out);
}

// round 5
// speedup vs baseline: 3.3115x; 1.0990x over previous
#include <cuda_runtime.h>
#include <cuda_bf16.h>
#include <math.h>
#include <stdint.h>

// Problem constants (B=8, S=2048, D=2048, H=2048, E=4, TOP_K=2)
#define NTOK 16384
#define DDIM 2048
#define HDIM 2048
#define NEXP 4
#define NCH  32              // K / 64 chunks

// Tile config: 128M x 256N CTA tile, 64x64 warp tiles (8 warps: 2M x 4N)
#define BM 128
#define BN 256
#define BK 64
#define TILE_A 16384                    // 128 rows x 128B
#define TILE_B 32768                    // 256 rows x 128B
#define STAGE_BYTES (2 * TILE_A + 2 * TILE_B)   // Ah Al Bh Bl = 98304
#define SMEM_TOTAL (1024 + 2 * STAGE_BYTES)     // 197632

// ---------------------------------------------------------------------------
// Scratch (static device arrays — no runtime allocation)
// ---------------------------------------------------------------------------
__device__ int   g_cnt[NEXP];
__device__ int   g_tok[NEXP][NTOK];
__device__ float g_wgt[NEXP][NTOK];
__device__ int   g_rank[NEXP][NTOK];

__device__ __nv_bfloat16 g_xh[(size_t)NTOK * DDIM];
__device__ __nv_bfloat16 g_xl[(size_t)NTOK * DDIM];
__device__ __nv_bfloat16 g_w1h[(size_t)NEXP * HDIM * DDIM];  // [e][n][k]
__device__ __nv_bfloat16 g_w1l[(size_t)NEXP * HDIM * DDIM];
__device__ __nv_bfloat16 g_w2h[(size_t)NEXP * HDIM * HDIM];  // [e][n][k]
__device__ __nv_bfloat16 g_w2l[(size_t)NEXP * HDIM * HDIM];
__device__ __nv_bfloat16 g_h1h[(size_t)NEXP * NTOK * HDIM];  // [e][slot][k]
__device__ __nv_bfloat16 g_h1l[(size_t)NEXP * NTOK * HDIM];
__device__ float g_outr[2][(size_t)NTOK * HDIM];             // rank-split partials

// ---------------------------------------------------------------------------
// Helpers
// ---------------------------------------------------------------------------
__device__ __forceinline__ uint32_t smem_u32(const void* p) {
    uint32_t a;
    asm("{ .reg .u64 t; cvta.to.shared.u64 t, %1; cvt.u32.u64 %0, t; }"
        : "=r"(a) : "l"(p));
    return a;
}
// XOR swizzle: 128B rows, 16B chunks; chunk ^= (row & 7)
__device__ __forceinline__ uint32_t swz(uint32_t row, uint32_t byteoff) {
    uint32_t c16 = byteoff >> 4, lo = byteoff & 15;
    return row * 128 + (((c16 ^ (row & 7)) & 7) << 4) + lo;
}
__device__ __forceinline__ void cp16(uint32_t saddr, const void* gaddr) {
    asm volatile("cp.async.cg.shared.global [%0], [%1], 16;" :: "r"(saddr), "l"(gaddr));
}
#define CP_COMMIT() asm volatile("cp.async.commit_group;" ::: "memory")
#define CP_WAIT0()  asm volatile("cp.async.wait_group 0;" ::: "memory")
#define CP_WAIT1()  asm volatile("cp.async.wait_group 1;" ::: "memory")

__device__ __forceinline__ void ldsm_x4(uint32_t* r, uint32_t addr) {
    asm volatile("ldmatrix.sync.aligned.m8n8.x4.shared.b16 {%0,%1,%2,%3}, [%4];"
        : "=r"(r[0]), "=r"(r[1]), "=r"(r[2]), "=r"(r[3]) : "r"(addr));
}
__device__ __forceinline__ void mma16816(float* d, const uint32_t* a, const uint32_t* b) {
    asm volatile(
        "mma.sync.aligned.m16n8k16.row.col.f32.bf16.bf16.f32 "
        "{%0,%1,%2,%3}, {%4,%5,%6,%7}, {%8,%9}, {%0,%1,%2,%3};"
        : "+f"(d[0]), "+f"(d[1]), "+f"(d[2]), "+f"(d[3])
        : "r"(a[0]), "r"(a[1]), "r"(a[2]), "r"(a[3]), "r"(b[0]), "r"(b[1]));
}

// ---------------------------------------------------------------------------
__global__ void reset_kernel() {
    if (threadIdx.x < NEXP) g_cnt[threadIdx.x] = 0;
}

// x fp32 -> bf16 hi/lo
__global__ void convert_x(const float4* __restrict__ x4, long n4) {
    long i = (long)blockIdx.x * blockDim.x + threadIdx.x;
    long st = (long)gridDim.x * blockDim.x;
    __nv_bfloat162* xh2 = (__nv_bfloat162*)g_xh;
    __nv_bfloat162* xl2 = (__nv_bfloat162*)g_xl;
    for (; i < n4; i += st) {
        float4 v = x4[i];
        __nv_bfloat16 h0 = __float2bfloat16(v.x), h1 = __float2bfloat16(v.y);
        __nv_bfloat16 h2 = __float2bfloat16(v.z), h3 = __float2bfloat16(v.w);
        __nv_bfloat16 l0 = __float2bfloat16(v.x - __bfloat162float(h0));
        __nv_bfloat16 l1 = __float2bfloat16(v.y - __bfloat162float(h1));
        __nv_bfloat16 l2 = __float2bfloat16(v.z - __bfloat162float(h2));
        __nv_bfloat16 l3 = __float2bfloat16(v.w - __bfloat162float(h3));
        xh2[2 * i]     = __nv_bfloat162(h0, h1);
        xh2[2 * i + 1] = __nv_bfloat162(h2, h3);
        xl2[2 * i]     = __nv_bfloat162(l0, l1);
        xl2[2 * i + 1] = __nv_bfloat162(l2, l3);
    }
}

// w [E][K][N] fp32 -> wt [E][N][K] bf16 hi/lo (K = N = 2048)
__global__ void transpose_w(const float* __restrict__ w, int which) {
    __shared__ float tile[32][33];
    int e = blockIdx.z;
    int n0 = blockIdx.x * 32, k0 = blockIdx.y * 32;
    const float* src = w + (size_t)e * DDIM * HDIM;
    int tx = threadIdx.x, ty = threadIdx.y;
#pragma unroll
    for (int i = 0; i < 4; i++) {
        int k = k0 + ty + i * 8;
        tile[ty + i * 8][tx] = src[(size_t)k * HDIM + n0 + tx];
    }
    __syncthreads();
    __nv_bfloat16* oh = which ? g_w2h : g_w1h;
    __nv_bfloat16* ol = which ? g_w2l : g_w1l;
#pragma unroll
    for (int i = 0; i < 4; i++) {
        int n = n0 + ty + i * 8;
        float v = tile[tx][ty + i * 8];
        __nv_bfloat16 h = __float2bfloat16(v);
        __nv_bfloat16 l = __float2bfloat16(v - __bfloat162float(h));
        size_t o = ((size_t)e * HDIM + n) * DDIM + k0 + tx;
        oh[o] = h; ol[o] = l;
    }
}

// ---------------------------------------------------------------------------
// Router (records rank of each slot: 0 = primary, 1 = secondary)
// ---------------------------------------------------------------------------
__global__ void router_kernel(const float* __restrict__ x,
                              const float* __restrict__ gw) {
    int warp = (blockIdx.x * blockDim.x + threadIdx.x) >> 5;
    int lane = threadIdx.x & 31;
    if (warp >= NTOK) return;
    const float* xr = x + (size_t)warp * DDIM;
    float a0 = 0.f, a1 = 0.f, a2 = 0.f, a3 = 0.f;
    for (int k = lane; k < DDIM; k += 32) {
        float xv = xr[k];
        a0 = fmaf(xv, gw[k], a0);
        a1 = fmaf(xv, gw[DDIM + k], a1);
        a2 = fmaf(xv, gw[2 * DDIM + k], a2);
        a3 = fmaf(xv, gw[3 * DDIM + k], a3);
    }
#pragma unroll
    for (int o = 16; o; o >>= 1) {
        a0 += __shfl_xor_sync(0xffffffffu, a0, o);
        a1 += __shfl_xor_sync(0xffffffffu, a1, o);
        a2 += __shfl_xor_sync(0xffffffffu, a2, o);
        a3 += __shfl_xor_sync(0xffffffffu, a3, o);
    }
    if (lane == 0) {
        float l[4] = {a0, a1, a2, a3};
        int i0 = 0;
#pragma unroll
        for (int e = 1; e < 4; e++) if (l[e] > l[i0]) i0 = e;
        int i1 = (i0 == 0) ? 1 : 0;
#pragma unroll
        for (int e = 0; e < 4; e++) if (e != i0 && l[e] > l[i1]) i1 = e;
        float w0 = 1.0f / (1.0f + expf(l[i1] - l[i0]));
        float w1 = 1.0f - w0;
        int s0 = atomicAdd(&g_cnt[i0], 1);
        g_tok[i0][s0] = warp; g_wgt[i0][s0] = w0; g_rank[i0][s0] = 0;
        int s1 = atomicAdd(&g_cnt[i1], 1);
        g_tok[i1][s1] = warp; g_wgt[i1][s1] = w1; g_rank[i1][s1] = 1;
    }
}

// ---------------------------------------------------------------------------
// GEMM core: bf16x3, m16n8k16, ldmatrix. 64x64 warp tile (4 mt x 8 nt).
// B fragments loaded pairwise and consumed immediately (register pressure).
// ---------------------------------------------------------------------------
__device__ __forceinline__ void compute_chunk(uint32_t base, int wm, int wn,
                                              int lane, float acc[4][8][4]) {
    uint32_t aH = base;
    uint32_t aL = base + TILE_A;
    uint32_t bH = base + 2 * TILE_A;
    uint32_t bL = base + 2 * TILE_A + TILE_B;

    uint32_t a_row  = (uint32_t)(wm * 64) + (lane & 15);
    uint32_t a_kb   = (uint32_t)((lane >> 4) << 4);
    uint32_t b_row0 = (uint32_t)(wn * 64) + (((lane >> 4) & 1) << 3) + (lane & 7);
    uint32_t b_kb   = (uint32_t)(((lane >> 3) & 1) << 4);

#pragma unroll
    for (int s = 0; s < 4; s++) {
        uint32_t boff = s * 32;
        uint32_t ah[4][4], al[4][4];
#pragma unroll
        for (int mt = 0; mt < 4; mt++) {
            uint32_t off = swz(a_row + mt * 16, boff + a_kb);
            ldsm_x4(ah[mt], aH + off);
            ldsm_x4(al[mt], aL + off);
        }
#pragma unroll
        for (int p = 0; p < 4; p++) {          // p covers n-tiles 2p, 2p+1
            uint32_t off = swz(b_row0 + p * 16, boff + b_kb);
            uint32_t rh[4], rl[4];
            ldsm_x4(rh, bH + off);
            ldsm_x4(rl, bL + off);
#pragma unroll
            for (int mt = 0; mt < 4; mt++) {
                mma16816(acc[mt][2 * p],     ah[mt], rh);
                mma16816(acc[mt][2 * p + 1], ah[mt], rh + 2);
                mma16816(acc[mt][2 * p],     ah[mt], rl);
                mma16816(acc[mt][2 * p + 1], ah[mt], rl + 2);
                mma16816(acc[mt][2 * p],     al[mt], rh);
                mma16816(acc[mt][2 * p + 1], al[mt], rh + 2);
            }
        }
    }
}

// ---------------------------------------------------------------------------
// GEMM1: h1[e][m][:] = gelu(x[tok] @ w1[e] + b1[e]) -> bf16 hi/lo
// ---------------------------------------------------------------------------
__global__ void __launch_bounds__(256, 1)
moe_gemm1(const float* __restrict__ b1) {
    int e = blockIdx.z;
    int cnt = g_cnt[e];
    int m0 = blockIdx.y * BM;
    if (m0 >= cnt) return;
    int n0 = blockIdx.x * BN;

    __shared__ int s_tok[BM];
    extern __shared__ char dynsm[];
    uint32_t ab = (smem_u32(dynsm) + 1023) & ~1023u;

    int tid = threadIdx.x;
    int wid = tid >> 5, lane = tid & 31;
    int wm = wid & 1, wn = wid >> 1;

    if (tid < BM) {
        int s = m0 + tid; if (s > cnt - 1) s = cnt - 1;
        s_tok[tid] = g_tok[e][s];
    }
    __syncthreads();

    const __nv_bfloat16* wh = g_w1h + (size_t)e * HDIM * DDIM;
    const __nv_bfloat16* wl = g_w1l + (size_t)e * HDIM * DDIM;

    float acc[4][8][4];
#pragma unroll
    for (int i = 0; i < 4; i++)
#pragma unroll
        for (int j = 0; j < 8; j++)
#pragma unroll
            for (int k = 0; k < 4; k++) acc[i][j][k] = 0.f;

    int r = tid >> 3, c16 = tid & 7;
    auto load_chunk = [&](int c, uint32_t bufb) {
        int k0 = c * BK;
#pragma unroll
        for (int i = 0; i < 4; i++) {           // A: 128 rows
            int rr = r + i * 32;
            uint32_t so = swz((uint32_t)rr, (uint32_t)(c16 * 16));
            size_t go = (size_t)s_tok[rr] * DDIM + k0 + c16 * 8;
            cp16(ab + bufb + so, g_xh + go);
            cp16(ab + bufb + TILE_A + so, g_xl + go);
        }
#pragma unroll
        for (int i = 0; i < 8; i++) {           // B: 256 rows
            int rr = r + i * 32;
            uint32_t so = swz((uint32_t)rr, (uint32_t)(c16 * 16));
            size_t gb = (size_t)(n0 + rr) * DDIM + k0 + c16 * 8;
            cp16(ab + bufb + 2 * TILE_A + so, wh + gb);
            cp16(ab + bufb + 2 * TILE_A + TILE_B + so, wl + gb);
        }
        CP_COMMIT();
    };

    load_chunk(0, 0);
    for (int c = 0; c < NCH; c++) {
        if (c + 1 < NCH) {
            load_chunk(c + 1, (uint32_t)((c + 1) & 1) * STAGE_BYTES);
            CP_WAIT1();
        } else {
            CP_WAIT0();
        }
        __syncthreads();
        compute_chunk(ab + (uint32_t)(c & 1) * STAGE_BYTES, wm, wn, lane, acc);
        __syncthreads();
    }

    // Epilogue: bias + exact GELU -> bf16 hi/lo -> global
    int g = lane >> 2, tig = lane & 3;
    __nv_bfloat16* h1h = g_h1h + (size_t)e * NTOK * HDIM;
    __nv_bfloat16* h1l = g_h1l + (size_t)e * NTOK * HDIM;
    const float* bias = b1 + (size_t)e * HDIM;
#pragma unroll
    for (int nt = 0; nt < 8; nt++) {
        int n = n0 + wn * 64 + nt * 8 + tig * 2;
        float bv0 = bias[n], bv1 = bias[n + 1];
#pragma unroll
        for (int mt = 0; mt < 4; mt++) {
#pragma unroll
            for (int half = 0; half < 2; half++) {
                int m = m0 + wm * 64 + mt * 16 + g + half * 8;
                if (m < cnt) {
                    float v0 = acc[mt][nt][half * 2 + 0] + bv0;
                    float v1 = acc[mt][nt][half * 2 + 1] + bv1;
                    float g0 = 0.5f * v0 * (1.0f + erff(v0 * 0.70710678118654752f));
                    float g1 = 0.5f * v1 * (1.0f + erff(v1 * 0.70710678118654752f));
                    __nv_bfloat16 h0 = __float2bfloat16(g0);
                    __nv_bfloat16 h1 = __float2bfloat16(g1);
                    __nv_bfloat16 l0 = __float2bfloat16(g0 - __bfloat162float(h0));
                    __nv_bfloat16 l1 = __float2bfloat16(g1 - __bfloat162float(h1));
                    uint32_t hp = (uint32_t)__bfloat16_as_ushort(h0) |
                                  ((uint32_t)__bfloat16_as_ushort(h1) << 16);
                    uint32_t lp = (uint32_t)__bfloat16_as_ushort(l0) |
                                  ((uint32_t)__bfloat16_as_ushort(l1) << 16);
                    *(uint32_t*)(h1h + (size_t)m * HDIM + n) = hp;
                    *(uint32_t*)(h1l + (size_t)m * HDIM + n) = lp;
                }
            }
        }
    }
}

// ---------------------------------------------------------------------------
// GEMM2: g_outr[rank][tok][:] = wgt * (h1[e] @ w2[e] + b2[e])
// Single launch over all experts; rank-split output -> no races, no RMW.
// ---------------------------------------------------------------------------
__global__ void __launch_bounds__(256, 1)
moe_gemm2(const float* __restrict__ b2) {
    int e = blockIdx.z;
    int cnt = g_cnt[e];
    int m0 = blockIdx.y * BM;
    if (m0 >= cnt) return;
    int n0 = blockIdx.x * BN;

    __shared__ int   s_tok[BM];
    __shared__ float s_wgt[BM];
    __shared__ int   s_rnk[BM];
    extern __shared__ char dynsm[];
    uint32_t ab = (smem_u32(dynsm) + 1023) & ~1023u;

    int tid = threadIdx.x;
    int wid = tid >> 5, lane = tid & 31;
    int wm = wid & 1, wn = wid >> 1;

    if (tid < BM) {
        int s = m0 + tid; if (s > cnt - 1) s = cnt - 1;
        s_tok[tid] = g_tok[e][s];
        s_wgt[tid] = g_wgt[e][s];
        s_rnk[tid] = g_rank[e][s];
    }
    __syncthreads();

    const __nv_bfloat16* ah = g_h1h + (size_t)e * NTOK * HDIM;
    const __nv_bfloat16* al = g_h1l + (size_t)e * NTOK * HDIM;
    const __nv_bfloat16* wh = g_w2h + (size_t)e * HDIM * HDIM;
    const __nv_bfloat16* wl = g_w2l + (size_t)e * HDIM * HDIM;

    float acc[4][8][4];
#pragma unroll
    for (int i = 0; i < 4; i++)
#pragma unroll
        for (int j = 0; j < 8; j++)
#pragma unroll
            for (int k = 0; k < 4; k++) acc[i][j][k] = 0.f;

    int r = tid >> 3, c16 = tid & 7;
    auto load_chunk = [&](int c, uint32_t bufb) {
        int k0 = c * BK;
#pragma unroll
        for (int i = 0; i < 4; i++) {
            int rr = r + i * 32;
            uint32_t so = swz((uint32_t)rr, (uint32_t)(c16 * 16));
            int mm = m0 + rr; if (mm > cnt - 1) mm = cnt - 1;
            size_t go = (size_t)mm * HDIM + k0 + c16 * 8;
            cp16(ab + bufb + so, ah + go);
            cp16(ab + bufb + TILE_A + so, al + go);
        }
#pragma unroll
        for (int i = 0; i < 8; i++) {
            int rr = r + i * 32;
            uint32_t so = swz((uint32_t)rr, (uint32_t)(c16 * 16));
            size_t gb = (size_t)(n0 + rr) * HDIM + k0 + c16 * 8;
            cp16(ab + bufb + 2 * TILE_A + so, wh + gb);
            cp16(ab + bufb + 2 * TILE_A + TILE_B + so, wl + gb);
        }
        CP_COMMIT();
    };

    load_chunk(0, 0);
    for (int c = 0; c < NCH; c++) {
        if (c + 1 < NCH) {
            load_chunk(c + 1, (uint32_t)((c + 1) & 1) * STAGE_BYTES);
            CP_WAIT1();
        } else {
            CP_WAIT0();
        }
        __syncthreads();
        compute_chunk(ab + (uint32_t)(c & 1) * STAGE_BYTES, wm, wn, lane, acc);
        __syncthreads();
    }

    // Epilogue: (acc + b2) * wgt -> plain store into rank plane
    int g = lane >> 2, tig = lane & 3;
    const float* bias = b2 + (size_t)e * HDIM;
#pragma unroll
    for (int nt = 0; nt < 8; nt++) {
        int n = n0 + wn * 64 + nt * 8 + tig * 2;
        float bv0 = bias[n], bv1 = bias[n + 1];
#pragma unroll
        for (int mt = 0; mt < 4; mt++) {
#pragma unroll
            for (int half = 0; half < 2; half++) {
                int rl = wm * 64 + mt * 16 + g + half * 8;
                int m = m0 + rl;
                if (m < cnt) {
                    float w = s_wgt[rl];
                    float* dst = g_outr[s_rnk[rl]] + (size_t)s_tok[rl] * HDIM + n;
                    dst[0] = w * (acc[mt][nt][half * 2 + 0] + bv0);
                    dst[1] = w * (acc[mt][nt][half * 2 + 1] + bv1);
                }
            }
        }
    }
}

// ---------------------------------------------------------------------------
__global__ void combine_kernel(float4* __restrict__ out, long n4) {
    long i = (long)blockIdx.x * blockDim.x + threadIdx.x;
    long st = (long)gridDim.x * blockDim.x;
    const float4* r0 = (const float4*)g_outr[0];
    const float4* r1 = (const float4*)g_outr[1];
    for (; i < n4; i += st) {
        float4 a = r0[i], b = r1[i];
        out[i] = make_float4(a.x + b.x, a.y + b.y, a.z + b.z, a.w + b.w);
    }
}

// ---------------------------------------------------------------------------
extern "C" void kernel_launch(void* const* d_in, const int* in_sizes, int n_in,
                              void* d_out, int out_size) {
    const float* x  = (const float*)d_in[0];
    const float* gw = (const float*)d_in[1];
    const float* w1 = (const float*)d_in[2];
    const float* b1 = (const float*)d_in[3];
    const float* w2 = (const float*)d_in[4];
    const float* b2 = (const float*)d_in[5];
    float* out = (float*)d_out;

    cudaFuncSetAttribute(moe_gemm1, cudaFuncAttributeMaxDynamicSharedMemorySize, SMEM_TOTAL);
    cudaFuncSetAttribute(moe_gemm2, cudaFuncAttributeMaxDynamicSharedMemorySize, SMEM_TOTAL);

    reset_kernel<<<1, 32>>>();
    convert_x<<<2048, 256>>>((const float4*)x, (long)NTOK * DDIM / 4);
    transpose_w<<<dim3(64, 64, 4), dim3(32, 8)>>>(w1, 0);
    transpose_w<<<dim3(64, 64, 4), dim3(32, 8)>>>(w2, 1);
    router_kernel<<<NTOK / 8, 256>>>(x, gw);

    moe_gemm1<<<dim3(HDIM / BN, NTOK / BM, NEXP), 256, SMEM_TOTAL>>>(b1);
    moe_gemm2<<<dim3(HDIM / BN, NTOK / BM, NEXP), 256, SMEM_TOTAL>>>(b2);
    combine_kernel<<<2048, 256>>>((float4*)out, (long)out_size / 4);
}